// round 1
// baseline (speedup 1.0000x reference)
#include <cuda_runtime.h>

// Problem constants
#define BN_   10000
#define T_    8
#define C_    64
#define NM_   3
#define E_    160000
#define NTOT_ (T_ * BN_)        // 80000 node-rows
#define HTOT_ (NTOT_ * C_)      // 5,120,000

// Scratch (device globals: allocation-free rule)
__device__ __align__(16) float g_hnew[HTOT_];   // h after time conv (T,BN,C) flat
__device__ __align__(16) float g_A[HTOT_];      // h_new @ We1[0:64]  + b_e1
__device__ __align__(16) float g_B[HTOT_];      // h_new @ We1[64:128]
__device__ __align__(16) float g_agg[HTOT_];    // segment sums
__device__ __align__(16) float g_d2[E_];        // squared distances per base edge

// 8-point DFT twiddles: CT8[n] = cos(2*pi*n/8), ST8[n] = sin(2*pi*n/8)
__constant__ float CT8[8] = {1.f,  0.70710678118654752f, 0.f, -0.70710678118654752f,
                             -1.f, -0.70710678118654752f, 0.f,  0.70710678118654752f};
__constant__ float ST8[8] = {0.f,  0.70710678118654752f, 1.f,  0.70710678118654752f,
                             0.f, -0.70710678118654752f, -1.f, -0.70710678118654752f};

__device__ __forceinline__ float silu_f(float x)    { return x / (1.f + __expf(-x)); }
__device__ __forceinline__ float sigmoid_f(float x) { return 1.f / (1.f + __expf(-x)); }

// ---------------------------------------------------------------------------
// Kernel 1: TimeConv on h.  h_new = h + leaky_relu(spectral_conv(h), 0.2)
// Block = 256 threads = 4 node-groups of 64.  Full complex weights in smem.
// ---------------------------------------------------------------------------
__global__ void k_time_h(const float* __restrict__ h,
                         const float* __restrict__ whr,
                         const float* __restrict__ whi) {
    extern __shared__ float sm[];
    float* swr = sm;            // [3][64][64]  k*4096 + i*64 + o
    float* swi = sm + 12288;    // same layout
    float* sxf = sm + 24576;    // [4 grp][64 i][6]  (xr0,0, xr1,xi1, xr2,xi2)
    const int tid = threadIdx.x;

    // Stage weights (C,C,NM) -> [k][i][o]
    for (int idx = tid; idx < C_ * C_ * NM_; idx += blockDim.x) {
        int i   = idx / (C_ * NM_);
        int rem = idx - i * (C_ * NM_);
        int o   = rem / NM_;
        int k   = rem - o * NM_;
        int d   = k * (C_ * C_) + i * C_ + o;
        swr[d] = whr[idx];
        swi[d] = whi[idx];
    }
    __syncthreads();

    const int grp = tid >> 6;
    const int l   = tid & 63;

    for (int nb = blockIdx.x * 4; nb < BN_; nb += gridDim.x * 4) {
        int node = nb + grp;
        // Phase A: l = input channel i.  Forward rfft (3 modes).
        if (node < BN_) {
            float xv[8];
#pragma unroll
            for (int t = 0; t < 8; ++t) xv[t] = h[t * (BN_ * C_) + node * C_ + l];
            float xr0 = 0.f, xr1 = 0.f, xi1 = 0.f, xr2 = 0.f, xi2 = 0.f;
#pragma unroll
            for (int t = 0; t < 8; ++t) {
                xr0 += xv[t];
                xr1 += xv[t] * CT8[t];
                xi1 -= xv[t] * ST8[t];
                xr2 += xv[t] * CT8[(2 * t) & 7];
                xi2 -= xv[t] * ST8[(2 * t) & 7];
            }
            float* p = sxf + grp * 384 + l * 6;
            p[0] = xr0; p[1] = 0.f; p[2] = xr1; p[3] = xi1; p[4] = xr2; p[5] = xi2;
        }
        __syncthreads();
        // Phase B/C: l = output channel o.  Complex mix + irfft + leaky residual.
        if (node < BN_) {
            float omr[3] = {0.f, 0.f, 0.f};
            float omi[3] = {0.f, 0.f, 0.f};
            const float* xb = sxf + grp * 384;
            for (int i = 0; i < C_; ++i) {
#pragma unroll
                for (int k = 0; k < 3; ++k) {
                    float xr = xb[i * 6 + 2 * k];
                    float xi = xb[i * 6 + 2 * k + 1];
                    float wr = swr[k * 4096 + i * 64 + l];
                    float wi = swi[k * 4096 + i * 64 + l];
                    omr[k] += xr * wr - xi * wi;
                    omi[k] += xr * wi + xi * wr;
                }
            }
            // irfft(n=8): imag of DC bin discarded (numpy semantics); modes 3,4 are 0.
#pragma unroll
            for (int t = 0; t < 8; ++t) {
                float val = omr[0]
                    + 2.f * (omr[1] * CT8[t]           - omi[1] * ST8[t])
                    + 2.f * (omr[2] * CT8[(2 * t) & 7] - omi[2] * ST8[(2 * t) & 7]);
                val *= 0.125f;
                float lr = val > 0.f ? val : 0.2f * val;
                int off = t * (BN_ * C_) + node * C_ + l;
                g_hnew[off] = h[off] + lr;
            }
        }
        __syncthreads();
    }
}

// ---------------------------------------------------------------------------
// Kernel 2: TimeConvX on velocity (channels=1).  vel_new = v + spec(v).
// One thread per (node, dim). Writes directly into d_out tail.
// ---------------------------------------------------------------------------
__global__ void k_time_v(const float* __restrict__ vel,
                         const float* __restrict__ wvr,
                         const float* __restrict__ wvi,
                         float* __restrict__ out) {
    int j = blockIdx.x * blockDim.x + threadIdx.x;
    if (j >= BN_ * 3) return;
    int b = j / 3, d = j - b * 3;
    float xv[8];
#pragma unroll
    for (int t = 0; t < 8; ++t) xv[t] = vel[b * (T_ * 3) + t * 3 + d];
    float xr0 = 0.f, xr1 = 0.f, xi1 = 0.f, xr2 = 0.f, xi2 = 0.f;
#pragma unroll
    for (int t = 0; t < 8; ++t) {
        xr0 += xv[t];
        xr1 += xv[t] * CT8[t];
        xi1 -= xv[t] * ST8[t];
        xr2 += xv[t] * CT8[(2 * t) & 7];
        xi2 -= xv[t] * ST8[(2 * t) & 7];
    }
    float w0r = wvr[0];
    float w1r = wvr[1], w1i = wvi[1];
    float w2r = wvr[2], w2i = wvi[2];
    float yr0 = xr0 * w0r;                       // DC imag discarded by irfft
    float yr1 = xr1 * w1r - xi1 * w1i;
    float yi1 = xr1 * w1i + xi1 * w1r;
    float yr2 = xr2 * w2r - xi2 * w2i;
    float yi2 = xr2 * w2i + xi2 * w2r;
#pragma unroll
    for (int t = 0; t < 8; ++t) {
        float val = 0.125f * (yr0
            + 2.f * (yr1 * CT8[t]           - yi1 * ST8[t])
            + 2.f * (yr2 * CT8[(2 * t) & 7] - yi2 * ST8[(2 * t) & 7]));
        out[b * (T_ * 3) + t * 3 + d] = xv[t] + val;
    }
}

// ---------------------------------------------------------------------------
// Kernel 3: per-base-edge squared distance
// ---------------------------------------------------------------------------
__global__ void k_d2(const float* __restrict__ x, const int* __restrict__ ei) {
    int e = blockIdx.x * blockDim.x + threadIdx.x;
    if (e >= E_) return;
    int r = ei[e];
    int c = ei[E_ + e];
    float dx = x[r * 3 + 0] - x[c * 3 + 0];
    float dy = x[r * 3 + 1] - x[c * 3 + 1];
    float dz = x[r * 3 + 2] - x[c * 3 + 2];
    g_d2[e] = dx * dx + dy * dy + dz * dz;
}

// ---------------------------------------------------------------------------
// Kernel 4: per-node precompute A = h@We1_top + b_e1,  B = h@We1_bot.
// Also zeroes agg. Thread per node-row, weights in smem (broadcast reads).
// ---------------------------------------------------------------------------
__global__ void __launch_bounds__(128) k_ab(const float* __restrict__ We1,
                                            const float* __restrict__ be1) {
    __shared__ __align__(16) float sW[128 * 64];
    __shared__ float sb[64];
    int tid = threadIdx.x;
    for (int i = tid; i < 128 * 64; i += 128) sW[i] = We1[i];
    if (tid < 64) sb[tid] = be1[tid];
    __syncthreads();
    int n = blockIdx.x * 128 + tid;
    if (n >= NTOT_) return;

    const float4* hp = (const float4*)(g_hnew + n * 64);
    float hv[64];
#pragma unroll
    for (int q = 0; q < 16; ++q) {
        float4 v = hp[q];
        hv[4*q] = v.x; hv[4*q+1] = v.y; hv[4*q+2] = v.z; hv[4*q+3] = v.w;
    }
    // zero agg for this row
    float4 z = make_float4(0.f, 0.f, 0.f, 0.f);
    float4* agp = (float4*)(g_agg + n * 64);
#pragma unroll
    for (int q = 0; q < 16; ++q) agp[q] = z;

    float acc[64];
#pragma unroll
    for (int o = 0; o < 64; ++o) acc[o] = sb[o];
#pragma unroll
    for (int k = 0; k < 64; ++k) {
        float mk = hv[k];
        const float4* row = (const float4*)(sW + k * 64);
#pragma unroll
        for (int q = 0; q < 16; ++q) {
            float4 w = row[q];
            acc[4*q]   += mk * w.x;
            acc[4*q+1] += mk * w.y;
            acc[4*q+2] += mk * w.z;
            acc[4*q+3] += mk * w.w;
        }
    }
    float4* ap = (float4*)(g_A + n * 64);
#pragma unroll
    for (int q = 0; q < 16; ++q)
        ap[q] = make_float4(acc[4*q], acc[4*q+1], acc[4*q+2], acc[4*q+3]);

#pragma unroll
    for (int o = 0; o < 64; ++o) acc[o] = 0.f;
#pragma unroll
    for (int k = 0; k < 64; ++k) {
        float mk = hv[k];
        const float4* row = (const float4*)(sW + (64 + k) * 64);
#pragma unroll
        for (int q = 0; q < 16; ++q) {
            float4 w = row[q];
            acc[4*q]   += mk * w.x;
            acc[4*q+1] += mk * w.y;
            acc[4*q+2] += mk * w.z;
            acc[4*q+3] += mk * w.w;
        }
    }
    float4* bp = (float4*)(g_B + n * 64);
#pragma unroll
    for (int q = 0; q < 16; ++q)
        bp[q] = make_float4(acc[4*q], acc[4*q+1], acc[4*q+2], acc[4*q+3]);
}

// ---------------------------------------------------------------------------
// Kernel 5: edge messages (the hot kernel). Thread per (t, edge).
// m1 = silu(A[rb] + B[cb] + d2*We1_last)   (b_e1 folded into A)
// m2 = silu(m1 @ We2 + b_e2); gate = sigmoid(m2 . Wg + bg)
// agg[rb] += gate * m2  (atomics)
// ---------------------------------------------------------------------------
__global__ void __launch_bounds__(128) k_edge(const int* __restrict__ ei,
                                              const float* __restrict__ We1,
                                              const float* __restrict__ We2,
                                              const float* __restrict__ be2,
                                              const float* __restrict__ Wg,
                                              const float* __restrict__ bg) {
    __shared__ __align__(16) float sW2[64 * 64];
    __shared__ __align__(16) float swl[64];
    __shared__ __align__(16) float sg[64];
    __shared__ __align__(16) float sb2[64];
    int tid = threadIdx.x;
    for (int i = tid; i < 64 * 64; i += 128) sW2[i] = We2[i];
    if (tid < 64) {
        swl[tid] = We1[128 * 64 + tid];  // row 128 of We1 (d2 row)
        sg[tid]  = Wg[tid];
        sb2[tid] = be2[tid];
    }
    __syncthreads();

    int e = blockIdx.x * 128 + tid;
    if (e >= T_ * E_) return;
    int t = e / E_;
    int j = e - t * E_;
    int rb = t * BN_ + __ldg(ei + j);
    int cb = t * BN_ + __ldg(ei + E_ + j);
    float dd = g_d2[j];

    const float4* Ap  = (const float4*)(g_A + rb * 64);
    const float4* Bp  = (const float4*)(g_B + cb * 64);
    const float4* wlp = (const float4*)swl;

    float m1[64];
#pragma unroll
    for (int q = 0; q < 16; ++q) {
        float4 a = Ap[q], b = Bp[q], w = wlp[q];
        m1[4*q]   = silu_f(a.x + b.x + dd * w.x);
        m1[4*q+1] = silu_f(a.y + b.y + dd * w.y);
        m1[4*q+2] = silu_f(a.z + b.z + dd * w.z);
        m1[4*q+3] = silu_f(a.w + b.w + dd * w.w);
    }

    float m2[64];
#pragma unroll
    for (int o = 0; o < 64; ++o) m2[o] = sb2[o];
#pragma unroll
    for (int k = 0; k < 64; ++k) {
        float mk = m1[k];
        const float4* row = (const float4*)(sW2 + k * 64);
#pragma unroll
        for (int q = 0; q < 16; ++q) {
            float4 w = row[q];
            m2[4*q]   += mk * w.x;
            m2[4*q+1] += mk * w.y;
            m2[4*q+2] += mk * w.z;
            m2[4*q+3] += mk * w.w;
        }
    }

    float gacc = bg[0];
#pragma unroll
    for (int o = 0; o < 64; ++o) {
        m2[o] = silu_f(m2[o]);
        gacc += m2[o] * sg[o];
    }
    float gate = sigmoid_f(gacc);

    float* ag = g_agg + rb * 64;
#pragma unroll
    for (int o = 0; o < 64; ++o) atomicAdd(ag + o, gate * m2[o]);
}

// ---------------------------------------------------------------------------
// Kernel 6: node update.  upd = silu([h_new, agg] @ Wn1 + b1) @ Wn2 + b2
// h_out = h_new + upd -> d_out head. Thread per node-row.
// ---------------------------------------------------------------------------
__global__ void __launch_bounds__(128) k_node(const float* __restrict__ Wn1,
                                              const float* __restrict__ bn1,
                                              const float* __restrict__ Wn2,
                                              const float* __restrict__ bn2,
                                              float* __restrict__ out) {
    extern __shared__ float smn[];
    float* sW1  = smn;           // 8192
    float* sW2  = smn + 8192;    // 4096
    float* sb1  = smn + 12288;   // 64
    float* sb2n = smn + 12352;   // 64
    int tid = threadIdx.x;
    for (int i = tid; i < 8192; i += 128) sW1[i] = Wn1[i];
    for (int i = tid; i < 4096; i += 128) sW2[i] = Wn2[i];
    if (tid < 64) { sb1[tid] = bn1[tid]; sb2n[tid] = bn2[tid]; }
    __syncthreads();

    int n = blockIdx.x * 128 + tid;
    if (n >= NTOT_) return;

    float hv[64], av[64];
    const float4* hp = (const float4*)(g_hnew + n * 64);
    const float4* gp = (const float4*)(g_agg + n * 64);
#pragma unroll
    for (int q = 0; q < 16; ++q) {
        float4 v = hp[q];
        hv[4*q] = v.x; hv[4*q+1] = v.y; hv[4*q+2] = v.z; hv[4*q+3] = v.w;
        float4 a = gp[q];
        av[4*q] = a.x; av[4*q+1] = a.y; av[4*q+2] = a.z; av[4*q+3] = a.w;
    }

    float u[64];
#pragma unroll
    for (int o = 0; o < 64; ++o) u[o] = sb1[o];
#pragma unroll
    for (int k = 0; k < 64; ++k) {
        float mk = hv[k];
        const float4* row = (const float4*)(sW1 + k * 64);
#pragma unroll
        for (int q = 0; q < 16; ++q) {
            float4 w = row[q];
            u[4*q]   += mk * w.x;
            u[4*q+1] += mk * w.y;
            u[4*q+2] += mk * w.z;
            u[4*q+3] += mk * w.w;
        }
    }
#pragma unroll
    for (int k = 0; k < 64; ++k) {
        float mk = av[k];
        const float4* row = (const float4*)(sW1 + (64 + k) * 64);
#pragma unroll
        for (int q = 0; q < 16; ++q) {
            float4 w = row[q];
            u[4*q]   += mk * w.x;
            u[4*q+1] += mk * w.y;
            u[4*q+2] += mk * w.z;
            u[4*q+3] += mk * w.w;
        }
    }
#pragma unroll
    for (int o = 0; o < 64; ++o) u[o] = silu_f(u[o]);

    // second layer, reuse av as accumulator (av is dead)
#pragma unroll
    for (int o = 0; o < 64; ++o) av[o] = sb2n[o];
#pragma unroll
    for (int k = 0; k < 64; ++k) {
        float mk = u[k];
        const float4* row = (const float4*)(sW2 + k * 64);
#pragma unroll
        for (int q = 0; q < 16; ++q) {
            float4 w = row[q];
            av[4*q]   += mk * w.x;
            av[4*q+1] += mk * w.y;
            av[4*q+2] += mk * w.z;
            av[4*q+3] += mk * w.w;
        }
    }

    float4* op = (float4*)(out + (size_t)n * 64);
#pragma unroll
    for (int q = 0; q < 16; ++q)
        op[q] = make_float4(hv[4*q] + av[4*q],   hv[4*q+1] + av[4*q+1],
                            hv[4*q+2] + av[4*q+2], hv[4*q+3] + av[4*q+3]);
}

// ---------------------------------------------------------------------------
extern "C" void kernel_launch(void* const* d_in, const int* in_sizes, int n_in,
                              void* d_out, int out_size) {
    const float* h   = (const float*)d_in[0];
    const float* x   = (const float*)d_in[1];
    const float* vel = (const float*)d_in[2];
    const int*   ei  = (const int*)d_in[3];
    const float* whr = (const float*)d_in[4];
    const float* whi = (const float*)d_in[5];
    const float* wvr = (const float*)d_in[6];
    const float* wvi = (const float*)d_in[7];
    const float* We1 = (const float*)d_in[8];
    const float* be1 = (const float*)d_in[9];
    const float* We2 = (const float*)d_in[10];
    const float* be2 = (const float*)d_in[11];
    const float* Wg  = (const float*)d_in[12];
    const float* bg  = (const float*)d_in[13];
    const float* Wn1 = (const float*)d_in[14];
    const float* bn1 = (const float*)d_in[15];
    const float* Wn2 = (const float*)d_in[16];
    const float* bn2 = (const float*)d_in[17];
    float* out = (float*)d_out;

    (void)in_sizes; (void)n_in; (void)out_size;

    const int smem_h    = 26112 * 4;   // 104448 B
    const int smem_node = 12416 * 4;   // 49664 B
    cudaFuncSetAttribute(k_time_h, cudaFuncAttributeMaxDynamicSharedMemorySize, smem_h);
    cudaFuncSetAttribute(k_node,   cudaFuncAttributeMaxDynamicSharedMemorySize, smem_node);

    // 1) time conv on h -> g_hnew
    k_time_h<<<625, 256, smem_h>>>(h, whr, whi);
    // 2) velocity conv -> d_out tail (independent)
    k_time_v<<<(BN_ * 3 + 255) / 256, 256>>>(vel, wvr, wvi, out + HTOT_);
    // 3) edge squared distances
    k_d2<<<(E_ + 255) / 256, 256>>>(x, ei);
    // 4) per-node A/B precompute + agg zero
    k_ab<<<(NTOT_ + 127) / 128, 128>>>(We1, be1);
    // 5) edge messages + atomic aggregate
    k_edge<<<(T_ * E_ + 127) / 128, 128>>>(ei, We1, We2, be2, Wg, bg);
    // 6) node update -> d_out head
    k_node<<<(NTOT_ + 127) / 128, 128, smem_node>>>(Wn1, bn1, Wn2, bn2, out);
}